// round 12
// baseline (speedup 1.0000x reference)
#include <cuda_runtime.h>
#include <math.h>

#define Bn   4
#define Hn   192
#define Wn   192
#define Qn   160
#define En   96
#define Mn   96
#define Kn   4
#define HW   (Hn*Wn)          /* 36864 */
#define NPIX (Bn*HW)          /* 147456 */

#define DICE_BLOCKS  576      /* per batch: 576 blocks * 8 warps * 8 px = 36864 */
#define OCC_BLOCKS   576      /* 576 * 256 = 147456 threads */
#define SMALL_BLOCKS 64

// Deterministic partial-sum scratch (fully overwritten every call; no init needed)
__device__ double g_dice[Bn][DICE_BLOCKS][2];  // [b][block][0]=num, [1]=sum_true
__device__ double g_occ[OCC_BLOCKS];
__device__ double g_small[SMALL_BLOCKS][3];    // class, bce, nll

__device__ __forceinline__ float softplusf(float x) {
    // logaddexp(0,x) = max(x,0) + log1p(exp(-|x|))
    return fmaxf(x, 0.0f) + log1pf(__expf(-fabsf(x)));
}

__device__ __forceinline__ double block_reduce(double v, double* sm) {
    int tid = threadIdx.x;
    sm[tid] = v;
    __syncthreads();
    for (int s = blockDim.x >> 1; s > 0; s >>= 1) {
        if (tid < s) sm[tid] += sm[tid + s];
        __syncthreads();
    }
    double r = sm[0];
    __syncthreads();
    return r;
}

// ---------------------------------------------------------------------------
// Small losses: class BCE (640), MVN NLL (384), 7x7-window mask BCE (18816)
// ---------------------------------------------------------------------------
__global__ void small_kernel(const float* __restrict__ iel,
                             const float* __restrict__ true_seg,
                             const float* __restrict__ bin_logits,
                             const float* __restrict__ inc_pts,
                             const float* __restrict__ positions,
                             const float* __restrict__ chol,
                             const int*   __restrict__ mq,
                             const int*   __restrict__ me)
{
    __shared__ double sm[256];
    const int NCLASS = Bn * Qn;            // 640
    const int NNLL   = Bn * Mn;            // 384
    const int NBCE   = Bn * Mn * 49;       // 18816
    const int total  = NCLASS + NNLL + NBCE;

    double s_class = 0.0, s_nll = 0.0, s_bce = 0.0;

    for (int i = blockIdx.x * blockDim.x + threadIdx.x; i < total;
         i += gridDim.x * blockDim.x) {
        if (i < NCLASS) {
            int b = i / Qn, q = i % Qn;
            float x = iel[i];
            bool lab = false;
            const int* mqb = mq + b * Mn;
            #pragma unroll 8
            for (int m = 0; m < Mn; m++) {
                if (mqb[m] == q) { lab = true; break; }
            }
            float z = lab ? 1.0f : 0.0f;
            float w = lab ? 1.0f : 0.1f;
            s_class += (double)(w * (softplusf(x) - x * z));
        } else if (i < NCLASS + NNLL) {
            int j = i - NCLASS;
            int b = j / Mn, m = j % Mn;
            int e = me[b * Mn + m];
            int q = mq[b * Mn + m];
            float p0 = inc_pts[(b * En + e) * 2 + 0];
            float p1 = inc_pts[(b * En + e) * 2 + 1];
            float c0 = positions[(b * Qn + q) * 2 + 0];
            float c1 = positions[(b * Qn + q) * 2 + 1];
            float l00 = chol[(b * Qn + q) * 4 + 0];
            float l10 = chol[(b * Qn + q) * 4 + 2];
            float l11 = chol[(b * Qn + q) * 4 + 3];
            float d0 = p0 - c0, d1 = p1 - c1;
            float z0 = d0 / l00;
            float z1 = (d1 - l10 * z0) / l11;
            float nll = 0.5f * (z0 * z0 + z1 * z1)
                      + 1.8378770664093453f    /* log(2*pi) */
                      + logf(l00) + logf(l11);
            if (isinf(nll)) nll = 1e7f;
            s_nll += (double)nll;
        } else {
            int k = i - NCLASS - NNLL;
            int b = k / (Mn * 49);
            int r = k % (Mn * 49);
            int m = r / 49;
            int w49 = r % 49;
            int wy = w49 / 7 - 3;
            int wx = w49 % 7 - 3;
            int e = me[b * Mn + m];
            int q = mq[b * Mn + m];
            float p0 = inc_pts[(b * En + e) * 2 + 0];
            float p1 = inc_pts[(b * En + e) * 2 + 1];
            int row = (int)floorf(p0) + wy;
            int col = (int)floorf(p1) + wx;
            size_t pixbase = ((size_t)(b * Hn + row) * Wn + col);
            float tv = true_seg[pixbase * En + e];
            float lg = bin_logits[pixbase * Qn + q];
            s_bce += (double)(softplusf(lg) - lg * tv);
        }
    }

    double rc = block_reduce(s_class, sm);
    double rb = block_reduce(s_bce, sm);
    double rn = block_reduce(s_nll, sm);
    if (threadIdx.x == 0) {
        g_small[blockIdx.x][0] = rc;
        g_small[blockIdx.x][1] = rb;
        g_small[blockIdx.x][2] = rn;
    }
}

// ---------------------------------------------------------------------------
// Occupancy cross-entropy: per-pixel log_softmax over K=4, pick true class
// ---------------------------------------------------------------------------
__global__ void occ_kernel(const float4* __restrict__ occ_logits,
                           const int*    __restrict__ occ_true)
{
    __shared__ double sm[256];
    double s = 0.0;
    for (int i = blockIdx.x * blockDim.x + threadIdx.x; i < NPIX;
         i += gridDim.x * blockDim.x) {
        float4 v = occ_logits[i];
        int t = occ_true[i];
        float mx = fmaxf(fmaxf(v.x, v.y), fmaxf(v.z, v.w));
        float se = __expf(v.x - mx) + __expf(v.y - mx)
                 + __expf(v.z - mx) + __expf(v.w - mx);
        float xt = (t == 0) ? v.x : (t == 1) ? v.y : (t == 2) ? v.z : v.w;
        s += (double)(xt - mx - logf(se));   // picked log-prob
    }
    double r = block_reduce(s, sm);
    if (threadIdx.x == 0) g_occ[blockIdx.x] = r;
}

// ---------------------------------------------------------------------------
// Dice main pass: warp-per-pixel. Gather 96 portion logits (of 160),
// softmax over m via warp shuffles, gather 96 true values, accumulate
// num = sum 2*t*p and sum_true per batch. den = sum_true + H*W (softmax
// sums to 1, matched_e is a full permutation of E).
// ---------------------------------------------------------------------------
__global__ void dice_kernel(const float* __restrict__ true_seg,
                            const float* __restrict__ por_logits,
                            const int*   __restrict__ mq,
                            const int*   __restrict__ me)
{
    __shared__ int s_mq[Mn], s_me[Mn];
    __shared__ double s_num[8], s_tv[8];

    const int b   = blockIdx.y;
    const int tid = threadIdx.x;
    if (tid < Mn)            s_mq[tid]       = mq[b * Mn + tid];
    else if (tid < 2 * Mn)   s_me[tid - Mn]  = me[b * Mn + tid - Mn];
    __syncthreads();

    const int warp = tid >> 5, lane = tid & 31;
    const int gw = blockIdx.x * 8 + warp;          // 0..4607 within batch
    const int WARPS_PER_BATCH = DICE_BLOCKS * 8;   // 4608

    const int m0 = s_mq[lane], m1 = s_mq[lane + 32], m2 = s_mq[lane + 64];
    const int e0 = s_me[lane], e1 = s_me[lane + 32], e2 = s_me[lane + 64];

    const float* __restrict__ porB = por_logits + (size_t)b * HW * Qn;
    const float* __restrict__ tvB  = true_seg  + (size_t)b * HW * En;

    double num_acc = 0.0, tv_acc = 0.0;

    #pragma unroll
    for (int it = 0; it < 8; it++) {
        int pix = gw + it * WARPS_PER_BATCH;
        const float* pp = porB + (size_t)pix * Qn;
        const float* tp = tvB  + (size_t)pix * En;

        float x0 = __ldg(pp + m0), x1 = __ldg(pp + m1), x2 = __ldg(pp + m2);
        float t0 = __ldg(tp + e0), t1 = __ldg(tp + e1), t2 = __ldg(tp + e2);

        float mx = fmaxf(fmaxf(x0, x1), x2);
        #pragma unroll
        for (int o = 16; o; o >>= 1) mx = fmaxf(mx, __shfl_xor_sync(~0u, mx, o));

        float ex0 = __expf(x0 - mx), ex1 = __expf(x1 - mx), ex2 = __expf(x2 - mx);
        float se = ex0 + ex1 + ex2;
        float dt = t0 * ex0 + t1 * ex1 + t2 * ex2;
        float tv = t0 + t1 + t2;
        #pragma unroll
        for (int o = 16; o; o >>= 1) {
            se += __shfl_xor_sync(~0u, se, o);
            dt += __shfl_xor_sync(~0u, dt, o);
            tv += __shfl_xor_sync(~0u, tv, o);
        }
        num_acc += (double)(2.0f * dt / se);
        tv_acc  += (double)tv;
    }

    if (lane == 0) { s_num[warp] = num_acc; s_tv[warp] = tv_acc; }
    __syncthreads();
    if (tid == 0) {
        double n = 0.0, t = 0.0;
        #pragma unroll
        for (int w = 0; w < 8; w++) { n += s_num[w]; t += s_tv[w]; }
        g_dice[b][blockIdx.x][0] = n;
        g_dice[b][blockIdx.x][1] = t;
    }
}

// ---------------------------------------------------------------------------
// Final combine: fold all partials, write scalar
// ---------------------------------------------------------------------------
__global__ void final_kernel(float* __restrict__ out)
{
    __shared__ double sm[256];
    const int tid = threadIdx.x;
    double v;

    v = 0.0; for (int i = tid; i < SMALL_BLOCKS; i += 256) v += g_small[i][0];
    double class_s = block_reduce(v, sm);
    v = 0.0; for (int i = tid; i < SMALL_BLOCKS; i += 256) v += g_small[i][1];
    double bce_s = block_reduce(v, sm);
    v = 0.0; for (int i = tid; i < SMALL_BLOCKS; i += 256) v += g_small[i][2];
    double nll_s = block_reduce(v, sm);
    v = 0.0; for (int i = tid; i < OCC_BLOCKS; i += 256) v += g_occ[i];
    double occ_s = block_reduce(v, sm);

    double dice = 0.0;
    for (int b = 0; b < Bn; b++) {
        double v1 = 0.0, v2 = 0.0;
        for (int i = tid; i < DICE_BLOCKS; i += 256) {
            v1 += g_dice[b][i][0];
            v2 += g_dice[b][i][1];
        }
        double num = block_reduce(v1, sm);
        double tvs = block_reduce(v2, sm);
        double den = tvs + (double)HW;       // softmax sums to 1 per pixel
        dice += 1.0 - (num + 1.0) / (den + 1.0);
    }

    if (tid == 0) {
        double class_loss = class_s / (double)(Bn * Qn);
        double bce_loss   = bce_s   / (double)(Bn * Mn * 49);
        double nll_loss   = nll_s   / (double)(Bn * Mn);
        double occ_loss   = -occ_s  / (double)NPIX;
        double dice_loss  = dice    / (double)Bn;
        out[0] = (float)(class_loss + bce_loss + dice_loss + nll_loss + occ_loss);
    }
}

// ---------------------------------------------------------------------------
extern "C" void kernel_launch(void* const* d_in, const int* in_sizes, int n_in,
                              void* d_out, int out_size)
{
    const float* iel  = (const float*)d_in[0];   // is_electron_logit [B*Q]
    const float* tseg = (const float*)d_in[1];   // true_segmap [B,H,W,E]
    const float* binl = (const float*)d_in[2];   // binary_mask_logits [B,H,W,Q]
    const float* porl = (const float*)d_in[3];   // portion_logits [B,H,W,Q]
    const float* inc  = (const float*)d_in[4];   // incidence_points [B,E,2]
    const float* pos  = (const float*)d_in[5];   // positions [B,Q,2]
    const float* chl  = (const float*)d_in[6];   // chol [B,Q,2,2]
    const float* occl = (const float*)d_in[7];   // occupancy_logits [B,H,W,K]
    const int*   occt = (const int*)d_in[8];     // occupancy_true [B,H,W]
    const int*   mq   = (const int*)d_in[9];     // matched_q [B,M]
    const int*   me   = (const int*)d_in[10];    // matched_e [B,E]

    small_kernel<<<SMALL_BLOCKS, 256>>>(iel, tseg, binl, inc, pos, chl, mq, me);
    occ_kernel<<<OCC_BLOCKS, 256>>>((const float4*)occl, occt);
    dice_kernel<<<dim3(DICE_BLOCKS, Bn), 256>>>(tseg, porl, mq, me);
    final_kernel<<<1, 256>>>((float*)d_out);
}

// round 13
// speedup vs baseline: 1.0033x; 1.0033x over previous
#include <cuda_runtime.h>
#include <math.h>

#define Bn   4
#define Hn   192
#define Wn   192
#define Qn   160
#define En   96
#define Mn   96
#define Kn   4
#define HW   (Hn*Wn)          /* 36864 */
#define NPIX (Bn*HW)          /* 147456 */

#define DICE_BLOCKS  576      /* per batch: 576 blocks * 8 warps * 8 px = 36864 */
#define OCC_BLOCKS   576      /* 576 * 256 = 147456 threads */
#define SMALL_BLOCKS 64

// Deterministic partial-sum scratch (fully overwritten every call; no init needed)
__device__ double g_dice[Bn][DICE_BLOCKS][2];  // [b][block][0]=num, [1]=sum_true
__device__ double g_occ[OCC_BLOCKS];
__device__ double g_small[SMALL_BLOCKS][3];    // class, bce, nll

__device__ __forceinline__ float softplusf(float x) {
    // logaddexp(0,x) = max(x,0) + log1p(exp(-|x|))
    return fmaxf(x, 0.0f) + log1pf(__expf(-fabsf(x)));
}

__device__ __forceinline__ double block_reduce(double v, double* sm) {
    int tid = threadIdx.x;
    sm[tid] = v;
    __syncthreads();
    for (int s = blockDim.x >> 1; s > 0; s >>= 1) {
        if (tid < s) sm[tid] += sm[tid + s];
        __syncthreads();
    }
    double r = sm[0];
    __syncthreads();
    return r;
}

// ---------------------------------------------------------------------------
// Small losses: class BCE (640), MVN NLL (384), 7x7-window mask BCE (18816)
// ---------------------------------------------------------------------------
__global__ void small_kernel(const float* __restrict__ iel,
                             const float* __restrict__ true_seg,
                             const float* __restrict__ bin_logits,
                             const float* __restrict__ inc_pts,
                             const float* __restrict__ positions,
                             const float* __restrict__ chol,
                             const int*   __restrict__ mq,
                             const int*   __restrict__ me)
{
    __shared__ double sm[256];
    const int NCLASS = Bn * Qn;            // 640
    const int NNLL   = Bn * Mn;            // 384
    const int NBCE   = Bn * Mn * 49;       // 18816
    const int total  = NCLASS + NNLL + NBCE;

    double s_class = 0.0, s_nll = 0.0, s_bce = 0.0;

    for (int i = blockIdx.x * blockDim.x + threadIdx.x; i < total;
         i += gridDim.x * blockDim.x) {
        if (i < NCLASS) {
            int b = i / Qn, q = i % Qn;
            float x = iel[i];
            bool lab = false;
            const int* mqb = mq + b * Mn;
            #pragma unroll 8
            for (int m = 0; m < Mn; m++) {
                if (mqb[m] == q) { lab = true; break; }
            }
            float z = lab ? 1.0f : 0.0f;
            float w = lab ? 1.0f : 0.1f;
            s_class += (double)(w * (softplusf(x) - x * z));
        } else if (i < NCLASS + NNLL) {
            int j = i - NCLASS;
            int b = j / Mn, m = j % Mn;
            int e = me[b * Mn + m];
            int q = mq[b * Mn + m];
            float p0 = inc_pts[(b * En + e) * 2 + 0];
            float p1 = inc_pts[(b * En + e) * 2 + 1];
            float c0 = positions[(b * Qn + q) * 2 + 0];
            float c1 = positions[(b * Qn + q) * 2 + 1];
            float l00 = chol[(b * Qn + q) * 4 + 0];
            float l10 = chol[(b * Qn + q) * 4 + 2];
            float l11 = chol[(b * Qn + q) * 4 + 3];
            float d0 = p0 - c0, d1 = p1 - c1;
            float z0 = d0 / l00;
            float z1 = (d1 - l10 * z0) / l11;
            float nll = 0.5f * (z0 * z0 + z1 * z1)
                      + 1.8378770664093453f    /* log(2*pi) */
                      + logf(l00) + logf(l11);
            if (isinf(nll)) nll = 1e7f;
            s_nll += (double)nll;
        } else {
            int k = i - NCLASS - NNLL;
            int b = k / (Mn * 49);
            int r = k % (Mn * 49);
            int m = r / 49;
            int w49 = r % 49;
            int wy = w49 / 7 - 3;
            int wx = w49 % 7 - 3;
            int e = me[b * Mn + m];
            int q = mq[b * Mn + m];
            float p0 = inc_pts[(b * En + e) * 2 + 0];
            float p1 = inc_pts[(b * En + e) * 2 + 1];
            int row = (int)floorf(p0) + wy;
            int col = (int)floorf(p1) + wx;
            size_t pixbase = ((size_t)(b * Hn + row) * Wn + col);
            float tv = true_seg[pixbase * En + e];
            float lg = bin_logits[pixbase * Qn + q];
            s_bce += (double)(softplusf(lg) - lg * tv);
        }
    }

    double rc = block_reduce(s_class, sm);
    double rb = block_reduce(s_bce, sm);
    double rn = block_reduce(s_nll, sm);
    if (threadIdx.x == 0) {
        g_small[blockIdx.x][0] = rc;
        g_small[blockIdx.x][1] = rb;
        g_small[blockIdx.x][2] = rn;
    }
}

// ---------------------------------------------------------------------------
// Occupancy cross-entropy: per-pixel log_softmax over K=4, pick true class
// ---------------------------------------------------------------------------
__global__ void occ_kernel(const float4* __restrict__ occ_logits,
                           const int*    __restrict__ occ_true)
{
    __shared__ double sm[256];
    double s = 0.0;
    for (int i = blockIdx.x * blockDim.x + threadIdx.x; i < NPIX;
         i += gridDim.x * blockDim.x) {
        float4 v = occ_logits[i];
        int t = occ_true[i];
        float mx = fmaxf(fmaxf(v.x, v.y), fmaxf(v.z, v.w));
        float se = __expf(v.x - mx) + __expf(v.y - mx)
                 + __expf(v.z - mx) + __expf(v.w - mx);
        float xt = (t == 0) ? v.x : (t == 1) ? v.y : (t == 2) ? v.z : v.w;
        s += (double)(xt - mx - logf(se));   // picked log-prob
    }
    double r = block_reduce(s, sm);
    if (threadIdx.x == 0) g_occ[blockIdx.x] = r;
}

// ---------------------------------------------------------------------------
// Dice main pass: warp-per-pixel. Gather 96 portion logits (of 160),
// softmax over m via warp shuffles, gather 96 true values, accumulate
// num = sum 2*t*p and sum_true per batch. den = sum_true + H*W (softmax
// sums to 1, matched_e is a full permutation of E).
// ---------------------------------------------------------------------------
__global__ void dice_kernel(const float* __restrict__ true_seg,
                            const float* __restrict__ por_logits,
                            const int*   __restrict__ mq,
                            const int*   __restrict__ me)
{
    __shared__ int s_mq[Mn], s_me[Mn];
    __shared__ double s_num[8], s_tv[8];

    const int b   = blockIdx.y;
    const int tid = threadIdx.x;
    if (tid < Mn)            s_mq[tid]       = mq[b * Mn + tid];
    else if (tid < 2 * Mn)   s_me[tid - Mn]  = me[b * Mn + tid - Mn];
    __syncthreads();

    const int warp = tid >> 5, lane = tid & 31;
    const int gw = blockIdx.x * 8 + warp;          // 0..4607 within batch
    const int WARPS_PER_BATCH = DICE_BLOCKS * 8;   // 4608

    const int m0 = s_mq[lane], m1 = s_mq[lane + 32], m2 = s_mq[lane + 64];
    const int e0 = s_me[lane], e1 = s_me[lane + 32], e2 = s_me[lane + 64];

    const float* __restrict__ porB = por_logits + (size_t)b * HW * Qn;
    const float* __restrict__ tvB  = true_seg  + (size_t)b * HW * En;

    double num_acc = 0.0, tv_acc = 0.0;

    #pragma unroll
    for (int it = 0; it < 8; it++) {
        int pix = gw + it * WARPS_PER_BATCH;
        const float* pp = porB + (size_t)pix * Qn;
        const float* tp = tvB  + (size_t)pix * En;

        float x0 = __ldg(pp + m0), x1 = __ldg(pp + m1), x2 = __ldg(pp + m2);
        float t0 = __ldg(tp + e0), t1 = __ldg(tp + e1), t2 = __ldg(tp + e2);

        float mx = fmaxf(fmaxf(x0, x1), x2);
        #pragma unroll
        for (int o = 16; o; o >>= 1) mx = fmaxf(mx, __shfl_xor_sync(~0u, mx, o));

        float ex0 = __expf(x0 - mx), ex1 = __expf(x1 - mx), ex2 = __expf(x2 - mx);
        float se = ex0 + ex1 + ex2;
        float dt = t0 * ex0 + t1 * ex1 + t2 * ex2;
        float tv = t0 + t1 + t2;
        #pragma unroll
        for (int o = 16; o; o >>= 1) {
            se += __shfl_xor_sync(~0u, se, o);
            dt += __shfl_xor_sync(~0u, dt, o);
            tv += __shfl_xor_sync(~0u, tv, o);
        }
        num_acc += (double)(2.0f * dt / se);
        tv_acc  += (double)tv;
    }

    if (lane == 0) { s_num[warp] = num_acc; s_tv[warp] = tv_acc; }
    __syncthreads();
    if (tid == 0) {
        double n = 0.0, t = 0.0;
        #pragma unroll
        for (int w = 0; w < 8; w++) { n += s_num[w]; t += s_tv[w]; }
        g_dice[b][blockIdx.x][0] = n;
        g_dice[b][blockIdx.x][1] = t;
    }
}

// ---------------------------------------------------------------------------
// Final combine: fold all partials, write scalar
// ---------------------------------------------------------------------------
__global__ void final_kernel(float* __restrict__ out)
{
    __shared__ double sm[256];
    const int tid = threadIdx.x;
    double v;

    v = 0.0; for (int i = tid; i < SMALL_BLOCKS; i += 256) v += g_small[i][0];
    double class_s = block_reduce(v, sm);
    v = 0.0; for (int i = tid; i < SMALL_BLOCKS; i += 256) v += g_small[i][1];
    double bce_s = block_reduce(v, sm);
    v = 0.0; for (int i = tid; i < SMALL_BLOCKS; i += 256) v += g_small[i][2];
    double nll_s = block_reduce(v, sm);
    v = 0.0; for (int i = tid; i < OCC_BLOCKS; i += 256) v += g_occ[i];
    double occ_s = block_reduce(v, sm);

    double dice = 0.0;
    for (int b = 0; b < Bn; b++) {
        double v1 = 0.0, v2 = 0.0;
        for (int i = tid; i < DICE_BLOCKS; i += 256) {
            v1 += g_dice[b][i][0];
            v2 += g_dice[b][i][1];
        }
        double num = block_reduce(v1, sm);
        double tvs = block_reduce(v2, sm);
        double den = tvs + (double)HW;       // softmax sums to 1 per pixel
        dice += 1.0 - (num + 1.0) / (den + 1.0);
    }

    if (tid == 0) {
        double class_loss = class_s / (double)(Bn * Qn);
        double bce_loss   = bce_s   / (double)(Bn * Mn * 49);
        double nll_loss   = nll_s   / (double)(Bn * Mn);
        double occ_loss   = -occ_s  / (double)NPIX;
        double dice_loss  = dice    / (double)Bn;
        out[0] = (float)(class_loss + bce_loss + dice_loss + nll_loss + occ_loss);
    }
}

// ---------------------------------------------------------------------------
extern "C" void kernel_launch(void* const* d_in, const int* in_sizes, int n_in,
                              void* d_out, int out_size)
{
    const float* iel  = (const float*)d_in[0];   // is_electron_logit [B*Q]
    const float* tseg = (const float*)d_in[1];   // true_segmap [B,H,W,E]
    const float* binl = (const float*)d_in[2];   // binary_mask_logits [B,H,W,Q]
    const float* porl = (const float*)d_in[3];   // portion_logits [B,H,W,Q]
    const float* inc  = (const float*)d_in[4];   // incidence_points [B,E,2]
    const float* pos  = (const float*)d_in[5];   // positions [B,Q,2]
    const float* chl  = (const float*)d_in[6];   // chol [B,Q,2,2]
    const float* occl = (const float*)d_in[7];   // occupancy_logits [B,H,W,K]
    const int*   occt = (const int*)d_in[8];     // occupancy_true [B,H,W]
    const int*   mq   = (const int*)d_in[9];     // matched_q [B,M]
    const int*   me   = (const int*)d_in[10];    // matched_e [B,E]

    small_kernel<<<SMALL_BLOCKS, 256>>>(iel, tseg, binl, inc, pos, chl, mq, me);
    occ_kernel<<<OCC_BLOCKS, 256>>>((const float4*)occl, occt);
    dice_kernel<<<dim3(DICE_BLOCKS, Bn), 256>>>(tseg, porl, mq, me);
    final_kernel<<<1, 256>>>((float*)d_out);
}